// round 12
// baseline (speedup 1.0000x reference)
#include <cuda_runtime.h>
#include <cuda_fp16.h>
#include <math.h>
#include <stdint.h>

#define SEQ     2048
#define DMODEL  1024
#define NH      16
#define DHEAD   64
#define FF      4096
#define MTOK    8192   // B*S
#define NBATCH  4
#define QKVLD   3072   // q|k|v concatenated row stride (halfs)

// ---------------- scratch (static device globals; no allocations) ----------------
__device__ __half g_qkv [(size_t)MTOK * QKVLD];
__device__ __half g_attn[(size_t)MTOK * DMODEL];
__device__ float  g_tmp [(size_t)MTOK * DMODEL];
__device__ float  g_y   [(size_t)MTOK * DMODEL];
__device__ __half g_yh  [(size_t)MTOK * DMODEL];
__device__ __half g_ff  [(size_t)MTOK * FF];
__device__ __half g_xh  [(size_t)MTOK * DMODEL];
__device__ __half g_wqkvT[(size_t)QKVLD * DMODEL];
__device__ __half g_woT [(size_t)DMODEL * DMODEL];
__device__ __half g_w1T [(size_t)FF * DMODEL];
__device__ __half g_w2T [(size_t)DMODEL * FF];
__device__ float  g_bqkv[QKVLD];

// ======================= helpers =======================
__device__ __forceinline__ uint32_t smem_u32(const void* p) {
    uint32_t a;
    asm("{ .reg .u64 t; cvta.to.shared.u64 t, %1; cvt.u32.u64 %0, t; }" : "=r"(a) : "l"(p));
    return a;
}
__device__ __forceinline__ void cp16(uint32_t dst, const void* src) {
    asm volatile("cp.async.cg.shared.global [%0], [%1], 16;" :: "r"(dst), "l"(src));
}
__device__ __forceinline__ void mma_f16(float* d, const uint32_t* a, const uint32_t* b) {
    asm volatile("mma.sync.aligned.m16n8k16.row.col.f32.f16.f16.f32 "
                 "{%0,%1,%2,%3}, {%4,%5,%6,%7}, {%8,%9}, {%0,%1,%2,%3};"
                 : "+f"(d[0]), "+f"(d[1]), "+f"(d[2]), "+f"(d[3])
                 : "r"(a[0]), "r"(a[1]), "r"(a[2]), "r"(a[3]), "r"(b[0]), "r"(b[1]));
}

// =================================================================================
// FP16 mma.sync GEMM: C[M,N] = A[M,K]*Bt[N,K]^T + bias (+resid fp32) (relu)
// CTA 128x128, BK=32, 256 threads / 8 warps, warp tile 64x32 (2m x 4n),
// 3-stage cp.async, ONE __syncthreads per chunk.
// ~120 regs/thread -> 2 CTAs/SM -> 16 warps/SM (4 per SMSP) to feed tensor pipe.
// =================================================================================
#define GH_LDH 40
#define GH_LDW 20
#define GH_STAGE_W (128 * GH_LDW)
#define GH_STAGES 3
#define GM_SMEM_BYTES (2 * GH_STAGES * GH_STAGE_W * 4)  // 61440

template<bool RELU, bool RESID, bool OUTH>
__global__ void __launch_bounds__(256, 2) mma_gemm(
    const __half* __restrict__ A, const __half* __restrict__ Bt,
    const float* __restrict__ bias, const float* __restrict__ resid,
    float* __restrict__ Cf, __half* __restrict__ Ch, int M, int N, int K)
{
    extern __shared__ __align__(16) uint32_t smw[];
    const uint32_t sb = smem_u32(smw);
    const int t    = threadIdx.x;
    const int lane = t & 31;
    const int w    = t >> 5;
    const int wm   = w & 1;          // 2 m-strips of 64
    const int wn   = w >> 1;         // 4 n-strips of 32
    const int qr   = lane >> 2;
    const int qc   = lane & 3;
    const int m0   = blockIdx.x * 128;
    const int n0   = blockIdx.y * 128;

    float acc[4][4][4];
#pragma unroll
    for (int mi = 0; mi < 4; mi++)
#pragma unroll
        for (int ni = 0; ni < 4; ni++)
#pragma unroll
            for (int k = 0; k < 4; k++) acc[mi][ni][k] = 0.f;

    const int NC = K >> 5;

    auto load_chunk = [&](int c, int s) {
        const int k0 = c << 5;
#pragma unroll
        for (int i = 0; i < 2; i++) {
            const int id = t + 256 * i;
            const int r = id >> 2, sg = id & 3;
            cp16(sb + 4u * (s * GH_STAGE_W + r * GH_LDW + sg * 4),
                 A + (size_t)(m0 + r) * K + k0 + sg * 8);
        }
#pragma unroll
        for (int i = 0; i < 2; i++) {
            const int id = t + 256 * i;
            const int r = id >> 2, sg = id & 3;
            cp16(sb + 4u * (GH_STAGES * GH_STAGE_W + s * GH_STAGE_W + r * GH_LDW + sg * 4),
                 Bt + (size_t)(n0 + r) * K + k0 + sg * 8);
        }
        asm volatile("cp.async.commit_group;" ::: "memory");
    };

    load_chunk(0, 0);
    load_chunk(1, 1);

    int scur = 0;
    for (int c = 0; c < NC; ++c) {
        if (c + 1 < NC)
            asm volatile("cp.async.wait_group 1;" ::: "memory");
        else
            asm volatile("cp.async.wait_group 0;" ::: "memory");
        __syncthreads();

        if (c + 2 < NC) {
            int s2 = scur + 2; if (s2 >= GH_STAGES) s2 -= GH_STAGES;
            load_chunk(c + 2, s2);
        }

        const uint32_t* Aw = smw + scur * GH_STAGE_W;
        const uint32_t* Bw = smw + GH_STAGES * GH_STAGE_W + scur * GH_STAGE_W;

#pragma unroll
        for (int kk = 0; kk < 2; kk++) {
            uint32_t af[4][4], bf[4][2];
#pragma unroll
            for (int mi = 0; mi < 4; mi++) {
                const int base = (wm * 64 + mi * 16 + qr) * GH_LDW + kk * 8 + qc;
                af[mi][0] = Aw[base];
                af[mi][1] = Aw[base + 8 * GH_LDW];
                af[mi][2] = Aw[base + 4];
                af[mi][3] = Aw[base + 8 * GH_LDW + 4];
            }
#pragma unroll
            for (int ni = 0; ni < 4; ni++) {
                const int bbx = (wn * 32 + ni * 8 + qr) * GH_LDW + kk * 8 + qc;
                bf[ni][0] = Bw[bbx];
                bf[ni][1] = Bw[bbx + 4];
            }
#pragma unroll
            for (int mi = 0; mi < 4; mi++)
#pragma unroll
                for (int ni = 0; ni < 4; ni++)
                    mma_f16(acc[mi][ni], af[mi], bf[ni]);
        }
        if (++scur == GH_STAGES) scur = 0;
    }

    // epilogue
#pragma unroll
    for (int mi = 0; mi < 4; mi++) {
        const int r0 = m0 + wm * 64 + mi * 16 + qr;
        const int r1 = r0 + 8;
#pragma unroll
        for (int ni = 0; ni < 4; ni++) {
            const int nb = n0 + wn * 32 + ni * 8 + qc * 2;
            const float b0 = bias[nb], b1 = bias[nb + 1];
            float2 v0, v1;
            v0.x = acc[mi][ni][0] + b0; v0.y = acc[mi][ni][1] + b1;
            v1.x = acc[mi][ni][2] + b0; v1.y = acc[mi][ni][3] + b1;
            if (RESID) {
                const float2 q0 = *(const float2*)(resid + (size_t)r0 * N + nb);
                const float2 q1 = *(const float2*)(resid + (size_t)r1 * N + nb);
                v0.x += q0.x; v0.y += q0.y; v1.x += q1.x; v1.y += q1.y;
            }
            if (RELU) {
                v0.x = fmaxf(v0.x, 0.f); v0.y = fmaxf(v0.y, 0.f);
                v1.x = fmaxf(v1.x, 0.f); v1.y = fmaxf(v1.y, 0.f);
            }
            if (OUTH) {
                *(__half2*)(Ch + (size_t)r0 * N + nb) = __floats2half2_rn(v0.x, v0.y);
                *(__half2*)(Ch + (size_t)r1 * N + nb) = __floats2half2_rn(v1.x, v1.y);
            } else {
                *(float2*)(Cf + (size_t)r0 * N + nb) = v0;
                *(float2*)(Cf + (size_t)r1 * N + nb) = v1;
            }
        }
    }
}

// =================================================================================
// Combined prep: weight transposes (fp16), x->fp16, bias concat. One launch.
// =================================================================================
__device__ __forceinline__ void tr32_tile(float (*tile)[33],
    const float* __restrict__ in, __half* __restrict__ out,
    int R, int C, int bx, int by, int tx, int ty)
{
    const int c0 = bx * 32, r0 = by * 32;
#pragma unroll
    for (int i = 0; i < 4; i++)
        tile[ty + 8 * i][tx] = in[(size_t)(r0 + ty + 8 * i) * C + c0 + tx];
    __syncthreads();
#pragma unroll
    for (int i = 0; i < 4; i++)
        out[(size_t)(c0 + ty + 8 * i) * R + r0 + tx] =
            __float2half_rn(tile[tx][ty + 8 * i]);
}

__global__ void __launch_bounds__(256) prep_kernel(
    const float* __restrict__ x,
    const float* __restrict__ wq, const float* __restrict__ wk, const float* __restrict__ wv,
    const float* __restrict__ bq, const float* __restrict__ bk, const float* __restrict__ bv,
    const float* __restrict__ wo, const float* __restrict__ w1, const float* __restrict__ w2,
    __half* __restrict__ xh, __half* __restrict__ wqkvT, __half* __restrict__ woT,
    __half* __restrict__ w1T, __half* __restrict__ w2T, float* __restrict__ bqkv)
{
    __shared__ float tile[32][33];
    const int bid = blockIdx.x;
    const int t = threadIdx.x, tx = t & 31, ty = t >> 5;

    if (bid < 1024) {
        tr32_tile(tile, wo, woT, DMODEL, DMODEL, bid & 31, bid >> 5, tx, ty);
    } else if (bid < 5120) {
        const int id = bid - 1024;
        tr32_tile(tile, w1, w1T, DMODEL, FF, id & 127, id >> 7, tx, ty);
    } else if (bid < 9216) {
        const int id = bid - 5120;
        tr32_tile(tile, w2, w2T, FF, DMODEL, id & 31, id >> 5, tx, ty);
    } else if (bid < 12288) {
        const int id = bid - 9216;
        const int z = id >> 6, rem = id & 63;
        const int zz = z / 16, h = z & 15;
        const float* src = (zz == 0 ? wq : (zz == 1 ? wk : wv)) + (size_t)h * DMODEL * DHEAD;
        __half* dst = wqkvT + ((size_t)(zz * 16 + h)) * DHEAD * DMODEL;
        tr32_tile(tile, src, dst, DMODEL, DHEAD, rem & 1, rem >> 1, tx, ty);
    } else if (bid < 20480) {
        const size_t i = ((size_t)(bid - 12288) * 256 + t) * 4;
        const float4 v = *(const float4*)(x + i);
        *(__half2*)(xh + i)     = __floats2half2_rn(v.x, v.y);
        *(__half2*)(xh + i + 2) = __floats2half2_rn(v.z, v.w);
    } else {
        const int i = (bid - 20480) * 256 + t;
        bqkv[i] = (i < 1024) ? bq[i] : ((i < 2048) ? bk[i - 1024] : bv[i - 2048]);
    }
}

// =================================================================================
// Fused flash attention, fp16 m16n8k16 mma. (unchanged from r10)
// =================================================================================
#define AH_LD  72
#define AH_LDW 36
#define AHT_QOFF 0
#define AHT_KOFF 4608
#define AHT_VOFF (4608 + 4608)
#define AHT_POFF (AHT_VOFF + 4608)
#define AHT_WORDS (AHT_POFF + 4608)
#define ATT_SMEM_BYTES (AHT_WORDS * 4)    // 73728

__global__ void __launch_bounds__(256, 2) attn_mma_kernel(
    const __half* __restrict__ qkv, __half* __restrict__ obuf)
{
    extern __shared__ __align__(16) uint32_t smu[];
    __half* smh = (__half*)smu;
    const uint32_t sb = smem_u32(smu);
    const int t = threadIdx.x, lane = t & 31, w = t >> 5;
    const int qr = lane >> 2, qc = lane & 3;
    const int mw = w * 16;
    const int bh = blockIdx.y;
    const int b = bh >> 4, hd = bh & 15;
    const int q0 = blockIdx.x * 128;

    {
        const float sc = 0.125f * 1.4426950408889634f;
        const int row = t >> 1, hoff = (t & 1) * 32;
        const __half* Q = qkv + (size_t)(b * SEQ + q0 + row) * QKVLD + hd * 64 + hoff;
        __half* dst = smh + (size_t)row * AH_LD + hoff;
#pragma unroll
        for (int c = 0; c < 32; c += 2) {
            const float2 f = __half22float2(*(const __half2*)(Q + c));
            *(__half2*)(dst + c) = __floats2half2_rn(f.x * sc, f.y * sc);
        }
    }

    const __half* Kp = qkv + (size_t)b * SEQ * QKVLD + 1024 + hd * 64;
    const __half* Vp = qkv + (size_t)b * SEQ * QKVLD + 2048 + hd * 64;

    auto load_k = [&](int kt, int s) {
#pragma unroll
        for (int i = 0; i < 2; i++) {
            const int id = t + 256 * i;
            const int r = id >> 3, sg = id & 7;
            cp16(sb + 4u * (AHT_KOFF + s * 2304 + r * AH_LDW) + sg * 16,
                 Kp + (size_t)(kt * 64 + r) * QKVLD + sg * 8);
        }
        asm volatile("cp.async.commit_group;" ::: "memory");
    };

    const int vkv = t >> 2, vseg = (t & 3) * 16;
    float4 vr0, vr1;
    auto ldg_v = [&](int kt) {
        const float4* p = (const float4*)(Vp + (size_t)(kt * 64 + vkv) * QKVLD + vseg);
        vr0 = p[0]; vr1 = p[1];
    };

    load_k(0, 0);
    ldg_v(0);
    __syncthreads();

    uint32_t qa[4][4];
    {
        const uint32_t* Qw = smu;
#pragma unroll
        for (int kk = 0; kk < 4; kk++) {
            const int base = (mw + qr) * AH_LDW + kk * 8 + qc;
            qa[kk][0] = Qw[base];
            qa[kk][1] = Qw[base + 8 * AH_LDW];
            qa[kk][2] = Qw[base + 4];
            qa[kk][3] = Qw[base + 8 * AH_LDW + 4];
        }
    }

    float o[8][4];
    float mrow[2] = { -INFINITY, -INFINITY };
    float lrow[2] = { 0.f, 0.f };
#pragma unroll
    for (int ni = 0; ni < 8; ni++)
#pragma unroll
        for (int k = 0; k < 4; k++) o[ni][k] = 0.f;

    const int NT = SEQ / 64;
    for (int kt = 0; kt < NT; kt++) {
        const int buf = kt & 1;

        {
            __half* vt = smh + 2 * (AHT_VOFF + buf * 2304);
            const __half* h0 = (const __half*)&vr0;
            const __half* h1 = (const __half*)&vr1;
#pragma unroll
            for (int j = 0; j < 8; j++) vt[(vseg + j) * AH_LD + vkv] = h0[j];
#pragma unroll
            for (int j = 0; j < 8; j++) vt[(vseg + 8 + j) * AH_LD + vkv] = h1[j];
        }

        asm volatile("cp.async.wait_group 0;" ::: "memory");
        __syncthreads();
        if (kt + 1 < NT) load_k(kt + 1, 1 - buf);
        ldg_v(kt + 1 < NT ? kt + 1 : NT - 1);

        const uint32_t* Kw = smu + AHT_KOFF + buf * 2304;

        float s[8][4];
#pragma unroll
        for (int ni = 0; ni < 8; ni++)
#pragma unroll
            for (int k = 0; k < 4; k++) s[ni][k] = 0.f;
#pragma unroll
        for (int kk = 0; kk < 4; kk++) {
#pragma unroll
            for (int ni = 0; ni < 8; ni++) {
                const int bbx = (ni * 8 + qr) * AH_LDW + kk * 8 + qc;
                uint32_t bfr[2] = { Kw[bbx], Kw[bbx + 4] };
                mma_f16(s[ni], qa[kk], bfr);
            }
        }

#pragma unroll
        for (int h2 = 0; h2 < 2; h2++) {
            float vm = -INFINITY;
#pragma unroll
            for (int ni = 0; ni < 8; ni++)
                vm = fmaxf(vm, fmaxf(s[ni][2 * h2], s[ni][2 * h2 + 1]));
            vm = fmaxf(vm, __shfl_xor_sync(0xffffffffu, vm, 1));
            vm = fmaxf(vm, __shfl_xor_sync(0xffffffffu, vm, 2));
            const float mn = fmaxf(mrow[h2], vm);
            const float alpha = exp2f(mrow[h2] - mn);
            mrow[h2] = mn;
            float rs = 0.f;
#pragma unroll
            for (int ni = 0; ni < 8; ni++) {
                const float p0 = exp2f(s[ni][2 * h2] - mn);
                const float p1 = exp2f(s[ni][2 * h2 + 1] - mn);
                s[ni][2 * h2] = p0; s[ni][2 * h2 + 1] = p1;
                rs += p0 + p1;
            }
            rs += __shfl_xor_sync(0xffffffffu, rs, 1);
            rs += __shfl_xor_sync(0xffffffffu, rs, 2);
            lrow[h2] = lrow[h2] * alpha + rs;
#pragma unroll
            for (int ni = 0; ni < 8; ni++) {
                o[ni][2 * h2]     *= alpha;
                o[ni][2 * h2 + 1] *= alpha;
            }
        }

        {
            __half* Ph = smh + 2 * AHT_POFF;
#pragma unroll
            for (int ni = 0; ni < 8; ni++) {
                *(__half2*)(Ph + (mw + qr) * AH_LD + ni * 8 + qc * 2) =
                    __floats2half2_rn(s[ni][0], s[ni][1]);
                *(__half2*)(Ph + (mw + qr + 8) * AH_LD + ni * 8 + qc * 2) =
                    __floats2half2_rn(s[ni][2], s[ni][3]);
            }
        }
        __syncwarp();

        const uint32_t* Pw = smu + AHT_POFF;
        const uint32_t* Vw = smu + AHT_VOFF + buf * 2304;
#pragma unroll
        for (int kk = 0; kk < 4; kk++) {
            uint32_t pa[4];
            const int base = (mw + qr) * AH_LDW + kk * 8 + qc;
            pa[0] = Pw[base];
            pa[1] = Pw[base + 8 * AH_LDW];
            pa[2] = Pw[base + 4];
            pa[3] = Pw[base + 8 * AH_LDW + 4];
#pragma unroll
            for (int ni = 0; ni < 8; ni++) {
                const int vb = (ni * 8 + qr) * AH_LDW + kk * 8 + qc;
                uint32_t bfr[2] = { Vw[vb], Vw[vb + 4] };
                mma_f16(o[ni], pa, bfr);
            }
        }
    }

    const float inv0 = 1.f / lrow[0];
    const float inv1 = 1.f / lrow[1];
    const int r0 = q0 + mw + qr;
    const int r1 = r0 + 8;
    __half* d0 = obuf + (size_t)(b * SEQ + r0) * DMODEL + hd * 64;
    __half* d1 = obuf + (size_t)(b * SEQ + r1) * DMODEL + hd * 64;
#pragma unroll
    for (int ni = 0; ni < 8; ni++) {
        const int nb = ni * 8 + qc * 2;
        *(__half2*)(d0 + nb) = __floats2half2_rn(o[ni][0] * inv0, o[ni][1] * inv0);
        *(__half2*)(d1 + nb) = __floats2half2_rn(o[ni][2] * inv1, o[ni][3] * inv1);
    }
}

// =================================================================================
// LayerNorm over D=1024; optional fp16 copy
// =================================================================================
template<bool OUTH>
__global__ void __launch_bounds__(256) ln_kernel(
    const float* __restrict__ in, const float* __restrict__ g,
    const float* __restrict__ b, float* __restrict__ out, __half* __restrict__ outh)
{
    const int row = blockIdx.x;
    const int tid = threadIdx.x;
    const float4 v = ((const float4*)(in + (size_t)row * DMODEL))[tid];

    float s  = v.x + v.y + v.z + v.w;
    float sq = v.x * v.x + v.y * v.y + v.z * v.z + v.w * v.w;
#pragma unroll
    for (int off = 16; off > 0; off >>= 1) {
        s  += __shfl_xor_sync(0xffffffffu, s,  off);
        sq += __shfl_xor_sync(0xffffffffu, sq, off);
    }
    __shared__ float ss[8], ssq[8];
    if ((tid & 31) == 0) { ss[tid >> 5] = s; ssq[tid >> 5] = sq; }
    __syncthreads();
    s = 0.f; sq = 0.f;
#pragma unroll
    for (int i = 0; i < 8; i++) { s += ss[i]; sq += ssq[i]; }

    const float mu   = s * (1.f / DMODEL);
    const float var  = sq * (1.f / DMODEL) - mu * mu;
    const float rstd = rsqrtf(var + 1e-5f);

    const float4 gg = ((const float4*)g)[tid];
    const float4 bb = ((const float4*)b)[tid];
    float4 r;
    r.x = (v.x - mu) * rstd * gg.x + bb.x;
    r.y = (v.y - mu) * rstd * gg.y + bb.y;
    r.z = (v.z - mu) * rstd * gg.z + bb.z;
    r.w = (v.w - mu) * rstd * gg.w + bb.w;
    ((float4*)(out + (size_t)row * DMODEL))[tid] = r;
    if (OUTH) {
        __half* oh = outh + (size_t)row * DMODEL + tid * 4;
        *(__half2*)(oh)     = __floats2half2_rn(r.x, r.y);
        *(__half2*)(oh + 2) = __floats2half2_rn(r.z, r.w);
    }
}

// =================================================================================
// Host launcher
// =================================================================================
extern "C" void kernel_launch(void* const* d_in, const int* in_sizes, int n_in,
                              void* d_out, int out_size)
{
    (void)in_sizes; (void)n_in; (void)out_size;
    const float* x     = (const float*)d_in[0];
    const float* wq    = (const float*)d_in[1];
    const float* bq    = (const float*)d_in[2];
    const float* wk    = (const float*)d_in[3];
    const float* bk    = (const float*)d_in[4];
    const float* wv    = (const float*)d_in[5];
    const float* bv    = (const float*)d_in[6];
    const float* wo    = (const float*)d_in[7];
    const float* bo    = (const float*)d_in[8];
    const float* ln1_g = (const float*)d_in[9];
    const float* ln1_b = (const float*)d_in[10];
    const float* w1    = (const float*)d_in[11];
    const float* b1    = (const float*)d_in[12];
    const float* w2    = (const float*)d_in[13];
    const float* b2    = (const float*)d_in[14];
    const float* ln2_g = (const float*)d_in[15];
    const float* ln2_b = (const float*)d_in[16];
    float* out = (float*)d_out;

    static __half *p_qkv = nullptr, *p_attn = nullptr, *p_yh = nullptr, *p_ff = nullptr,
                  *p_xh = nullptr, *p_wqkvT = nullptr, *p_woT = nullptr, *p_w1T = nullptr,
                  *p_w2T = nullptr;
    static float *p_tmp = nullptr, *p_y = nullptr, *p_bqkv = nullptr;
    if (!p_qkv) {
        cudaGetSymbolAddress((void**)&p_qkv,   g_qkv);
        cudaGetSymbolAddress((void**)&p_attn,  g_attn);
        cudaGetSymbolAddress((void**)&p_tmp,   g_tmp);
        cudaGetSymbolAddress((void**)&p_y,     g_y);
        cudaGetSymbolAddress((void**)&p_yh,    g_yh);
        cudaGetSymbolAddress((void**)&p_ff,    g_ff);
        cudaGetSymbolAddress((void**)&p_xh,    g_xh);
        cudaGetSymbolAddress((void**)&p_wqkvT, g_wqkvT);
        cudaGetSymbolAddress((void**)&p_woT,   g_woT);
        cudaGetSymbolAddress((void**)&p_w1T,   g_w1T);
        cudaGetSymbolAddress((void**)&p_w2T,   g_w2T);
        cudaGetSymbolAddress((void**)&p_bqkv,  g_bqkv);
        cudaFuncSetAttribute(attn_mma_kernel,
                             cudaFuncAttributeMaxDynamicSharedMemorySize, ATT_SMEM_BYTES);
        cudaFuncSetAttribute(mma_gemm<false, false, true>,
                             cudaFuncAttributeMaxDynamicSharedMemorySize, GM_SMEM_BYTES);
        cudaFuncSetAttribute(mma_gemm<false, true, false>,
                             cudaFuncAttributeMaxDynamicSharedMemorySize, GM_SMEM_BYTES);
        cudaFuncSetAttribute(mma_gemm<true, false, true>,
                             cudaFuncAttributeMaxDynamicSharedMemorySize, GM_SMEM_BYTES);
    }

    // 0) one combined prep launch
    prep_kernel<<<20492, 256>>>(x, wq, wk, wv, bq, bk, bv, wo, w1, w2,
                                p_xh, p_wqkvT, p_woT, p_w1T, p_w2T, p_bqkv);

    // 1) fused QKV projection -> fp16
    mma_gemm<false, false, true><<<dim3(MTOK / 128, QKVLD / 128), 256, GM_SMEM_BYTES>>>(
        p_xh, p_wqkvT, p_bqkv, nullptr, nullptr, p_qkv, MTOK, QKVLD, DMODEL);

    // 2) fused attention (fp16 mma) -> fp16
    attn_mma_kernel<<<dim3(SEQ / 128, NBATCH * NH), 256, ATT_SMEM_BYTES>>>(p_qkv, p_attn);

    // 3) output projection + bias + residual(x fp32) -> fp32
    mma_gemm<false, true, false><<<dim3(MTOK / 128, DMODEL / 128), 256, GM_SMEM_BYTES>>>(
        p_attn, p_woT, bo, x, p_tmp, nullptr, MTOK, DMODEL, DMODEL);

    // 4) LN1 -> y (fp32) + yh (fp16)
    ln_kernel<true><<<MTOK, 256>>>(p_tmp, ln1_g, ln1_b, p_y, p_yh);

    // 5) FFN1: relu(y*w1 + b1) -> fp16
    mma_gemm<true, false, true><<<dim3(MTOK / 128, FF / 128), 256, GM_SMEM_BYTES>>>(
        p_yh, p_w1T, b1, nullptr, nullptr, p_ff, MTOK, FF, DMODEL);

    // 6) FFN2: ff*w2 + b2 + residual(y fp32) -> fp32
    mma_gemm<false, true, false><<<dim3(MTOK / 128, DMODEL / 128), 256, GM_SMEM_BYTES>>>(
        p_ff, p_w2T, b2, p_y, p_tmp, nullptr, MTOK, DMODEL, FF);

    // 7) LN2 -> out
    ln_kernel<false><<<MTOK, 256>>>(p_tmp, ln2_g, ln2_b, out, nullptr);
}